// round 3
// baseline (speedup 1.0000x reference)
#include <cuda_runtime.h>

// ---------------- sizes ----------------
#define BATCH 256
#define NY 3686400              // 256*64*15*15
#define H1N (256*64*62*62)
#define H2N (256*64*31*31)

// fused feval smem: halo 64*18*18 + weight pairs 4ci*9*64co*2 + stats 256
#define HALO_FLOATS (64*324)            // 20736
#define WPAIR_FLOATS (4*9*64*2)         // 4608
#define STAT_FLOATS 256
#define FEV_SMEM_FLOATS (HALO_FLOATS + WPAIR_FLOATS + STAT_FLOATS)   // 25600
#define FEV_SMEM_BYTES (FEV_SMEM_FLOATS * 4)                          // 102400

// ---------------- scratch (device globals, no allocation) ----------------
__device__ float g_h1[H1N];
__device__ float g_h2[H2N];
__device__ float g_y[NY];
__device__ float g_t0[NY];
__device__ float g_k[6][NY];
__device__ float g_S1[64 * 225];
__device__ float g_S2[64 * 225];
__device__ float g_pool[256 * 64];

// ---------------- helpers ----------------
__inline__ __device__ float warpSum(float v) {
#pragma unroll
    for (int o = 16; o; o >>= 1) v += __shfl_xor_sync(0xffffffffu, v, o);
    return v;
}

__device__ __forceinline__ float2 ffma2(float2 a, float2 b, float2 c) {
    unsigned long long au = *reinterpret_cast<unsigned long long*>(&a);
    unsigned long long bu = *reinterpret_cast<unsigned long long*>(&b);
    unsigned long long cu = *reinterpret_cast<unsigned long long*>(&c);
    unsigned long long du;
    asm("fma.rn.f32x2 %0, %1, %2, %3;" : "=l"(du) : "l"(au), "l"(bu), "l"(cu));
    float2 d = *reinterpret_cast<float2*>(&du);
    return d;
}

// ---------------- conv1: 1->64, 3x3, valid, 64 -> 62 ----------------
__global__ void conv1_kernel(const float* __restrict__ x, float* __restrict__ out,
                             const float* __restrict__ w, const float* __restrict__ bias)
{
    __shared__ float sx[18][18];
    __shared__ float swt[64 * 9];
    __shared__ float sb[64];
    int b = blockIdx.y;
    int tileX = blockIdx.x & 3, tileY = blockIdx.x >> 2;
    int tx = threadIdx.x, ty = threadIdx.y;
    int tid = ty * 16 + tx;

    for (int s = tid; s < 576; s += 256) swt[s] = w[s];
    if (tid < 64) sb[tid] = bias[tid];

    const float* xb = x + (size_t)b * 64 * 64;
    int ox0 = tileX * 16, oy0 = tileY * 16;
    for (int s = tid; s < 18 * 18; s += 256) {
        int r = s / 18, c = s % 18;
        int iy = oy0 + r, ix = ox0 + c;
        sx[r][c] = (iy < 64 && ix < 64) ? xb[iy * 64 + ix] : 0.f;
    }
    __syncthreads();

    int ox = ox0 + tx, oy = oy0 + ty;
    if (ox >= 62 || oy >= 62) return;

    float v[9];
#pragma unroll
    for (int ky = 0; ky < 3; ky++)
#pragma unroll
        for (int kx = 0; kx < 3; kx++)
            v[ky * 3 + kx] = sx[ty + ky][tx + kx];

    float* ob = out + (size_t)b * 64 * 3844 + oy * 62 + ox;
#pragma unroll 4
    for (int co = 0; co < 64; co++) {
        float a = sb[co];
#pragma unroll
        for (int k = 0; k < 9; k++) a = fmaf(swt[co * 9 + k], v[k], a);
        ob[(size_t)co * 3844] = a;
    }
}

// ---------------- generic GroupNorm (big HW) ----------------
__global__ void gn_big_kernel(const float* __restrict__ in, float* __restrict__ out,
                              const float* __restrict__ gamma, const float* __restrict__ beta,
                              int HW, int relu)
{
    __shared__ float rs[8], rs2[8], stats[2];
    int bg = blockIdx.x;
    int c0 = (bg & 31) * 2;
    size_t base = (size_t)bg * 2 * HW;
    int n = 2 * HW;
    float s = 0.f, s2 = 0.f;
    for (int i = threadIdx.x; i < n; i += 256) {
        float v = in[base + i];
        s += v; s2 = fmaf(v, v, s2);
    }
    s = warpSum(s); s2 = warpSum(s2);
    int wi = threadIdx.x >> 5, lane = threadIdx.x & 31;
    if (lane == 0) { rs[wi] = s; rs2[wi] = s2; }
    __syncthreads();
    if (threadIdx.x == 0) {
        float a = 0.f, bb = 0.f;
#pragma unroll
        for (int i = 0; i < 8; i++) { a += rs[i]; bb += rs2[i]; }
        float mu = a / (float)n;
        stats[0] = mu;
        stats[1] = rsqrtf(bb / (float)n - mu * mu + 1e-5f);
    }
    __syncthreads();
    float mu = stats[0], inv = stats[1];
    float sc0 = inv * gamma[c0],     sh0 = beta[c0]     - mu * sc0;
    float sc1 = inv * gamma[c0 + 1], sh1 = beta[c0 + 1] - mu * sc1;
    for (int i = threadIdx.x; i < n; i += 256) {
        float v = in[base + i];
        float r = (i < HW) ? fmaf(v, sc0, sh0) : fmaf(v, sc1, sh1);
        if (relu) r = fmaxf(r, 0.f);
        out[base + i] = r;
    }
}

// ---------------- GroupNorm for 15x15, 1 warp per (b,g) ----------------
__global__ void gn225_kernel(const float* __restrict__ in, float* __restrict__ out,
                             const float* __restrict__ gamma, const float* __restrict__ beta,
                             int relu)
{
    int bg = blockIdx.x;
    int lane = threadIdx.x;
    size_t base = (size_t)bg * 450;
    int c0 = (bg & 31) * 2;
    float v[15];
    float s = 0.f, s2 = 0.f;
#pragma unroll
    for (int k = 0; k < 15; k++) {
        int i = k * 32 + lane;
        float xv = (i < 450) ? in[base + i] : 0.f;
        v[k] = xv;
        s += xv; s2 = fmaf(xv, xv, s2);
    }
    s = warpSum(s); s2 = warpSum(s2);
    float mu = s * (1.f / 450.f);
    float inv = rsqrtf(s2 * (1.f / 450.f) - mu * mu + 1e-5f);
    float sc0 = inv * gamma[c0],     sh0 = beta[c0]     - mu * sc0;
    float sc1 = inv * gamma[c0 + 1], sh1 = beta[c0 + 1] - mu * sc1;
#pragma unroll
    for (int k = 0; k < 15; k++) {
        int i = k * 32 + lane;
        if (i < 450) {
            float r = (i < 225) ? fmaf(v[k], sc0, sh0) : fmaf(v[k], sc1, sh1);
            if (relu) r = fmaxf(r, 0.f);
            out[base + i] = r;
        }
    }
}

// ---------------- conv 4x4 stride 2 pad 1 (64->64) ----------------
__global__ void conv4x4_kernel(const float* __restrict__ in, float* __restrict__ out,
                               const float* __restrict__ w, const float* __restrict__ bias,
                               int Hin, int Hout)
{
    __shared__ float sw[4 * 64 * 16];
    int b = blockIdx.z;
    int co0 = blockIdx.y * 4;
    int tid = threadIdx.x;
    for (int s = tid; s < 4096; s += 256) {
        int j = s >> 10;
        int ci = (s >> 4) & 63;
        int tp = s & 15;
        sw[s] = w[(((size_t)(co0 + j)) * 64 + ci) * 16 + tp];
    }
    __syncthreads();

    int p = blockIdx.x * 256 + tid;
    int HW = Hout * Hout;
    if (p >= HW) return;
    int oy = p / Hout, ox = p % Hout;

    float a0 = bias[co0], a1 = bias[co0 + 1], a2 = bias[co0 + 2], a3 = bias[co0 + 3];
    const float* inb = in + (size_t)b * 64 * Hin * Hin;

    for (int ci = 0; ci < 64; ci++) {
        const float* inc = inb + (size_t)ci * Hin * Hin;
        const float* sw0 = sw + ci * 16;
        const float* sw1 = sw + 1024 + ci * 16;
        const float* sw2 = sw + 2048 + ci * 16;
        const float* sw3 = sw + 3072 + ci * 16;
#pragma unroll
        for (int ky = 0; ky < 4; ky++) {
            int iy = oy * 2 - 1 + ky;
            if ((unsigned)iy < (unsigned)Hin) {
#pragma unroll
                for (int kx = 0; kx < 4; kx++) {
                    int ix = ox * 2 - 1 + kx;
                    if ((unsigned)ix < (unsigned)Hin) {
                        float v = __ldg(inc + iy * Hin + ix);
                        int tp = ky * 4 + kx;
                        a0 = fmaf(v, sw0[tp], a0);
                        a1 = fmaf(v, sw1[tp], a1);
                        a2 = fmaf(v, sw2[tp], a2);
                        a3 = fmaf(v, sw3[tp], a3);
                    }
                }
            }
        }
    }
    size_t ob = (((size_t)b * 64 + co0) * HW) + p;
    out[ob] = a0; out[ob + HW] = a1; out[ob + 2 * (size_t)HW] = a2; out[ob + 3 * (size_t)HW] = a3;
}

// ---------------- precompute S[co][p] ----------------
__global__ void precomp_s_kernel(const float* __restrict__ w, float* __restrict__ S)
{
    int co = blockIdx.x;
    int p = threadIdx.x;
    int y = p / 15, x = p % 15;
    float a = 0.f;
#pragma unroll
    for (int ky = 0; ky < 3; ky++) {
        int iy = y - 1 + ky;
        if ((unsigned)iy < 15u) {
#pragma unroll
            for (int kx = 0; kx < 3; kx++) {
                int ix = x - 1 + kx;
                if ((unsigned)ix < 15u) a += w[(size_t)co * 65 * 9 + ky * 3 + kx];
            }
        }
    }
    S[co * 225 + p] = a;
}

// ---------------- fused ODE function eval ----------------
// yin = y + sum cj*kj ; GN1+relu -> conv1(+b+tS1) -> GN2+relu -> conv2(+b+tS2) -> GN3 -> kout
// grid BATCH, block 256, dyn smem 102400B
// thread mapping: cog = tid>>4 (co0 = 4*cog), rowt = tid&15 (row; rowt==15 garbage)
__device__ __forceinline__ void conv_phase_f2(
    float* halo, float2* swp, const float* __restrict__ wglob,
    int tid, int co0, int rowt, float2 acc2[4][8])
{
    for (int cc = 0; cc < 16; cc++) {
        __syncthreads();
#pragma unroll 1
        for (int s = tid; s < 2304; s += 256) {
            int co = s & 63;
            int r = s >> 6;          // 0..35
            int k9 = r % 9;
            int ciL = r / 9;
            float wv = wglob[((size_t)co * 65 + (cc * 4 + ciL + 1)) * 9 + k9];
            swp[(ciL * 9 + k9) * 64 + co] = make_float2(wv, wv);
        }
        __syncthreads();
#pragma unroll
        for (int ciL = 0; ciL < 4; ciL++) {
            const float* hbase = halo + (cc * 4 + ciL) * 324;
#pragma unroll
            for (int ky = 0; ky < 3; ky++) {
                const float2* rp = (const float2*)(hbase + (rowt + ky) * 18);
                float2 e[9];
#pragma unroll
                for (int u = 0; u < 9; u++) e[u] = rp[u];
                float2 o[8];
#pragma unroll
                for (int u = 0; u < 8; u++) o[u] = make_float2(e[u].y, e[u + 1].x);
#pragma unroll
                for (int a = 0; a < 4; a++) {
                    int wb = (ciL * 9 + ky * 3) * 64 + co0 + a;
                    float2 w0 = swp[wb];
                    float2 w1 = swp[wb + 64];
                    float2 w2 = swp[wb + 128];
#pragma unroll
                    for (int u = 0; u < 8; u++) {
                        acc2[a][u] = ffma2(e[u],     w0, acc2[a][u]);
                        acc2[a][u] = ffma2(o[u],     w1, acc2[a][u]);
                        acc2[a][u] = ffma2(e[u + 1], w2, acc2[a][u]);
                    }
                }
            }
        }
    }
    __syncthreads();
}

__global__ void __launch_bounds__(256, 2)
feval_kernel(const float* __restrict__ y,
             const float* __restrict__ k0, const float* __restrict__ k1,
             const float* __restrict__ k2, const float* __restrict__ k3,
             const float* __restrict__ k4,
             float c0, float c1, float c2, float c3, float c4, int nk,
             const float* __restrict__ g1, const float* __restrict__ bb1,
             const float* __restrict__ w1, const float* __restrict__ b1,
             const float* __restrict__ S1g,
             const float* __restrict__ g2, const float* __restrict__ bb2,
             const float* __restrict__ w2, const float* __restrict__ b2,
             const float* __restrict__ S2g,
             const float* __restrict__ g3, const float* __restrict__ bb3,
             float t, float* __restrict__ kout)
{
    extern __shared__ float smem[];
    float* halo = smem;                                 // 64 x 18 x 18
    float2* swp = (float2*)(smem + HALO_FLOATS);        // weight pairs
    float* sums   = smem + HALO_FLOATS + WPAIR_FLOATS;  // 64
    float* sumsq  = sums + 64;                          // 64
    float* scv    = sums + 128;                         // 64
    float* shv    = sums + 192;                         // 64

    int tid = threadIdx.x;
    int b = blockIdx.x;
    size_t base = (size_t)b * 14400;
    int cog = tid >> 4, rowt = tid & 15;
    int co0 = cog * 4;

    // P0: zero halo
    float4* h4 = (float4*)halo;
    for (int i = tid; i < HALO_FLOATS / 4; i += 256) h4[i] = make_float4(0.f, 0.f, 0.f, 0.f);
    __syncthreads();

    // P1: combine prologue + GN1 stats; ch = tid>>2, q = tid&3
    {
        int ch = tid >> 2, q = tid & 3;
        float s = 0.f, s2 = 0.f;
        for (int j = q; j < 225; j += 4) {
            size_t idx = base + ch * 225 + j;
            float v = y[idx];
            if (nk > 0) v = fmaf(c0, k0[idx], v);
            if (nk > 1) v = fmaf(c1, k1[idx], v);
            if (nk > 2) v = fmaf(c2, k2[idx], v);
            if (nk > 3) v = fmaf(c3, k3[idx], v);
            if (nk > 4) v = fmaf(c4, k4[idx], v);
            halo[ch * 324 + (j / 15 + 1) * 18 + (j % 15) + 1] = v;
            s += v; s2 = fmaf(v, v, s2);
        }
        s  += __shfl_xor_sync(0xffffffffu, s, 1);
        s  += __shfl_xor_sync(0xffffffffu, s, 2);
        s2 += __shfl_xor_sync(0xffffffffu, s2, 1);
        s2 += __shfl_xor_sync(0xffffffffu, s2, 2);
        if (q == 0) { sums[ch] = s; sumsq[ch] = s2; }
        __syncthreads();
        if (tid < 32) {
            int ca = 2 * tid, cb = ca + 1;
            float mu = (sums[ca] + sums[cb]) * (1.f / 450.f);
            float var = (sumsq[ca] + sumsq[cb]) * (1.f / 450.f) - mu * mu;
            float inv = rsqrtf(var + 1e-5f);
            float sa = inv * g1[ca], sb2 = inv * g1[cb];
            scv[ca] = sa; shv[ca] = bb1[ca] - mu * sa;
            scv[cb] = sb2; shv[cb] = bb1[cb] - mu * sb2;
        }
        __syncthreads();
        float sc = scv[ch], sh = shv[ch];
        for (int j = q; j < 225; j += 4) {
            int hi = ch * 324 + (j / 15 + 1) * 18 + (j % 15) + 1;
            halo[hi] = fmaxf(fmaf(halo[hi], sc, sh), 0.f);
        }
    }
    // conv_phase leading syncthreads orders halo writes vs reads

    float2 acc2[4][8];

    // ---- conv1 ----
#pragma unroll
    for (int a = 0; a < 4; a++)
#pragma unroll
        for (int u = 0; u < 8; u++) acc2[a][u] = make_float2(0.f, 0.f);
    conv_phase_f2(halo, swp, w1, tid, co0, rowt, acc2);

    // ---- bias + t*S1, GN2 stats ----
    {
        float s[4] = {0.f, 0.f, 0.f, 0.f}, s2[4] = {0.f, 0.f, 0.f, 0.f};
        if (rowt < 15) {
#pragma unroll
            for (int a = 0; a < 4; a++) {
                float bv = b1[co0 + a];
                const float* Srow = S1g + (co0 + a) * 225 + rowt * 15;
#pragma unroll
                for (int u = 0; u < 8; u++) {
                    float v0 = acc2[a][u].x + bv + t * __ldg(Srow + 2 * u);
                    float v1 = (u < 7) ? acc2[a][u].y + bv + t * __ldg(Srow + 2 * u + 1) : 0.f;
                    acc2[a][u].x = v0; acc2[a][u].y = v1;
                    s[a] += v0 + v1;
                    s2[a] = fmaf(v0, v0, s2[a]); s2[a] = fmaf(v1, v1, s2[a]);
                }
            }
        }
#pragma unroll
        for (int a = 0; a < 4; a++) {
#pragma unroll
            for (int o = 8; o; o >>= 1) {
                s[a]  += __shfl_xor_sync(0xffffffffu, s[a], o);
                s2[a] += __shfl_xor_sync(0xffffffffu, s2[a], o);
            }
        }
        if (rowt == 0) {
#pragma unroll
            for (int a = 0; a < 4; a++) { sums[co0 + a] = s[a]; sumsq[co0 + a] = s2[a]; }
        }
        __syncthreads();
        if (tid < 32) {
            int ca = 2 * tid, cb = ca + 1;
            float mu = (sums[ca] + sums[cb]) * (1.f / 450.f);
            float var = (sumsq[ca] + sumsq[cb]) * (1.f / 450.f) - mu * mu;
            float inv = rsqrtf(var + 1e-5f);
            float sa = inv * g2[ca], sb2 = inv * g2[cb];
            scv[ca] = sa; shv[ca] = bb2[ca] - mu * sa;
            scv[cb] = sb2; shv[cb] = bb2[cb] - mu * sb2;
        }
        __syncthreads();
        if (rowt < 15) {
#pragma unroll
            for (int a = 0; a < 4; a++) {
                float sc = scv[co0 + a], sh = shv[co0 + a];
                float* hrow = halo + (co0 + a) * 324 + (rowt + 1) * 18 + 1;
#pragma unroll
                for (int u = 0; u < 8; u++) {
                    hrow[2 * u] = fmaxf(fmaf(acc2[a][u].x, sc, sh), 0.f);
                    if (u < 7) hrow[2 * u + 1] = fmaxf(fmaf(acc2[a][u].y, sc, sh), 0.f);
                }
            }
        }
    }

    // ---- conv2 ----
#pragma unroll
    for (int a = 0; a < 4; a++)
#pragma unroll
        for (int u = 0; u < 8; u++) acc2[a][u] = make_float2(0.f, 0.f);
    conv_phase_f2(halo, swp, w2, tid, co0, rowt, acc2);

    // ---- bias + t*S2, GN3 (no relu), write kout ----
    {
        float s[4] = {0.f, 0.f, 0.f, 0.f}, s2[4] = {0.f, 0.f, 0.f, 0.f};
        if (rowt < 15) {
#pragma unroll
            for (int a = 0; a < 4; a++) {
                float bv = b2[co0 + a];
                const float* Srow = S2g + (co0 + a) * 225 + rowt * 15;
#pragma unroll
                for (int u = 0; u < 8; u++) {
                    float v0 = acc2[a][u].x + bv + t * __ldg(Srow + 2 * u);
                    float v1 = (u < 7) ? acc2[a][u].y + bv + t * __ldg(Srow + 2 * u + 1) : 0.f;
                    acc2[a][u].x = v0; acc2[a][u].y = v1;
                    s[a] += v0 + v1;
                    s2[a] = fmaf(v0, v0, s2[a]); s2[a] = fmaf(v1, v1, s2[a]);
                }
            }
        }
#pragma unroll
        for (int a = 0; a < 4; a++) {
#pragma unroll
            for (int o = 8; o; o >>= 1) {
                s[a]  += __shfl_xor_sync(0xffffffffu, s[a], o);
                s2[a] += __shfl_xor_sync(0xffffffffu, s2[a], o);
            }
        }
        if (rowt == 0) {
#pragma unroll
            for (int a = 0; a < 4; a++) { sums[co0 + a] = s[a]; sumsq[co0 + a] = s2[a]; }
        }
        __syncthreads();
        if (tid < 32) {
            int ca = 2 * tid, cb = ca + 1;
            float mu = (sums[ca] + sums[cb]) * (1.f / 450.f);
            float var = (sumsq[ca] + sumsq[cb]) * (1.f / 450.f) - mu * mu;
            float inv = rsqrtf(var + 1e-5f);
            float sa = inv * g3[ca], sb2 = inv * g3[cb];
            scv[ca] = sa; shv[ca] = bb3[ca] - mu * sa;
            scv[cb] = sb2; shv[cb] = bb3[cb] - mu * sb2;
        }
        __syncthreads();
        if (rowt < 15) {
#pragma unroll
            for (int a = 0; a < 4; a++) {
                float sc = scv[co0 + a], sh = shv[co0 + a];
                float* orow = kout + base + (co0 + a) * 225 + rowt * 15;
#pragma unroll
                for (int u = 0; u < 8; u++) {
                    orow[2 * u] = fmaf(acc2[a][u].x, sc, sh);
                    if (u < 7) orow[2 * u + 1] = fmaf(acc2[a][u].y, sc, sh);
                }
            }
        }
    }
}

// ---------------- dopri final combine (per step): dst = y + sum cj*kj ----------------
__global__ void combine_kernel(const float4* __restrict__ y, float4* __restrict__ dst,
                               const float4* __restrict__ p0, const float4* __restrict__ p1,
                               const float4* __restrict__ p2, const float4* __restrict__ p3,
                               const float4* __restrict__ p4,
                               float c0, float c1, float c2, float c3, float c4)
{
    int i = blockIdx.x * 256 + threadIdx.x;
    float4 a = y[i];
    float4 t;
    t = p0[i]; a.x = fmaf(c0, t.x, a.x); a.y = fmaf(c0, t.y, a.y); a.z = fmaf(c0, t.z, a.z); a.w = fmaf(c0, t.w, a.w);
    t = p1[i]; a.x = fmaf(c1, t.x, a.x); a.y = fmaf(c1, t.y, a.y); a.z = fmaf(c1, t.z, a.z); a.w = fmaf(c1, t.w, a.w);
    t = p2[i]; a.x = fmaf(c2, t.x, a.x); a.y = fmaf(c2, t.y, a.y); a.z = fmaf(c2, t.z, a.z); a.w = fmaf(c2, t.w, a.w);
    t = p3[i]; a.x = fmaf(c3, t.x, a.x); a.y = fmaf(c3, t.y, a.y); a.z = fmaf(c3, t.z, a.z); a.w = fmaf(c3, t.w, a.w);
    t = p4[i]; a.x = fmaf(c4, t.x, a.x); a.y = fmaf(c4, t.y, a.y); a.z = fmaf(c4, t.z, a.z); a.w = fmaf(c4, t.w, a.w);
    dst[i] = a;
}

// ---------------- global mean pool ----------------
__global__ void pool_kernel(const float* __restrict__ in, float* __restrict__ out)
{
    int gw = (blockIdx.x * 256 + threadIdx.x) >> 5;
    int lane = threadIdx.x & 31;
    const float* p = in + (size_t)gw * 225;
    float s = 0.f;
    for (int i = lane; i < 225; i += 32) s += p[i];
    s = warpSum(s);
    if (lane == 0) out[gw] = s * (1.f / 225.f);
}

// ---------------- FC 64->10 ----------------
__global__ void fc_kernel(const float* __restrict__ pool, const float* __restrict__ w,
                          const float* __restrict__ bias, float* __restrict__ out)
{
    __shared__ float sp[64];
    int b = blockIdx.x;
    sp[threadIdx.x] = pool[b * 64 + threadIdx.x];
    __syncthreads();
    if (threadIdx.x < 10) {
        float a = bias[threadIdx.x];
#pragma unroll
        for (int c = 0; c < 64; c++) a = fmaf(sp[c], __ldg(&w[threadIdx.x * 64 + c]), a);
        out[b * 10 + threadIdx.x] = a;
    }
}

// ---------------- launch ----------------
extern "C" void kernel_launch(void* const* d_in, const int* in_sizes, int n_in,
                              void* d_out, int out_size)
{
    const float* x        = (const float*)d_in[0];
    const float* conv1_w  = (const float*)d_in[1];
    const float* conv1_b  = (const float*)d_in[2];
    const float* gn1_g    = (const float*)d_in[3];
    const float* gn1_b    = (const float*)d_in[4];
    const float* conv2_w  = (const float*)d_in[5];
    const float* conv2_b  = (const float*)d_in[6];
    const float* gn2_g    = (const float*)d_in[7];
    const float* gn2_b    = (const float*)d_in[8];
    const float* conv3_w  = (const float*)d_in[9];
    const float* conv3_b  = (const float*)d_in[10];
    const float* f_gn1_g  = (const float*)d_in[11];
    const float* f_gn1_b  = (const float*)d_in[12];
    const float* f_conv1_w= (const float*)d_in[13];
    const float* f_conv1_b= (const float*)d_in[14];
    const float* f_gn2_g  = (const float*)d_in[15];
    const float* f_gn2_b  = (const float*)d_in[16];
    const float* f_conv2_w= (const float*)d_in[17];
    const float* f_conv2_b= (const float*)d_in[18];
    const float* f_gn3_g  = (const float*)d_in[19];
    const float* f_gn3_b  = (const float*)d_in[20];
    const float* out_gn_g = (const float*)d_in[21];
    const float* out_gn_b = (const float*)d_in[22];
    const float* fc_w     = (const float*)d_in[23];
    const float* fc_b     = (const float*)d_in[24];
    float* out = (float*)d_out;

    float *h1, *h2, *y, *t0b, *kbase, *S1, *S2, *pool;
    cudaGetSymbolAddress((void**)&h1, g_h1);
    cudaGetSymbolAddress((void**)&h2, g_h2);
    cudaGetSymbolAddress((void**)&y, g_y);
    cudaGetSymbolAddress((void**)&t0b, g_t0);
    cudaGetSymbolAddress((void**)&kbase, g_k);
    cudaGetSymbolAddress((void**)&S1, g_S1);
    cudaGetSymbolAddress((void**)&S2, g_S2);
    cudaGetSymbolAddress((void**)&pool, g_pool);
    float* kk[6];
    for (int i = 0; i < 6; i++) kk[i] = kbase + (size_t)i * NY;

    cudaFuncSetAttribute(feval_kernel, cudaFuncAttributeMaxDynamicSharedMemorySize, FEV_SMEM_BYTES);

    // ---- downsampling ----
    conv1_kernel<<<dim3(16, BATCH), dim3(16, 16)>>>(x, h1, conv1_w, conv1_b);
    gn_big_kernel<<<BATCH * 32, 256>>>(h1, h1, gn1_g, gn1_b, 62 * 62, 1);
    conv4x4_kernel<<<dim3(4, 16, BATCH), 256>>>(h1, h2, conv2_w, conv2_b, 62, 31);
    gn_big_kernel<<<BATCH * 32, 256>>>(h2, h2, gn2_g, gn2_b, 31 * 31, 1);
    conv4x4_kernel<<<dim3(1, 16, BATCH), 256>>>(h2, y, conv3_w, conv3_b, 31, 15);

    precomp_s_kernel<<<64, 225>>>(f_conv1_w, S1);
    precomp_s_kernel<<<64, 225>>>(f_conv2_w, S2);

    auto feval = [&](float t, const float* p0, const float* p1, const float* p2,
                     const float* p3, const float* p4,
                     double c0, double c1, double c2, double c3, double c4,
                     int nk, float* kout) {
        feval_kernel<<<BATCH, 256, FEV_SMEM_BYTES>>>(
            y, p0 ? p0 : y, p1 ? p1 : y, p2 ? p2 : y, p3 ? p3 : y, p4 ? p4 : y,
            (float)c0, (float)c1, (float)c2, (float)c3, (float)c4, nk,
            f_gn1_g, f_gn1_b, f_conv1_w, f_conv1_b, S1,
            f_gn2_g, f_gn2_b, f_conv2_w, f_conv2_b, S2,
            f_gn3_g, f_gn3_b, t, kout);
    };

    const double hs = 1.0 / 8.0;
    for (int st = 0; st < 8; st++) {
        double T0 = st * hs;
        feval((float)T0, 0, 0, 0, 0, 0, 0, 0, 0, 0, 0, 0, kk[0]);
        feval((float)(T0 + hs / 5.0), kk[0], 0, 0, 0, 0,
              hs * (1.0 / 5.0), 0, 0, 0, 0, 1, kk[1]);
        feval((float)(T0 + 0.3 * hs), kk[0], kk[1], 0, 0, 0,
              hs * (3.0 / 40.0), hs * (9.0 / 40.0), 0, 0, 0, 2, kk[2]);
        feval((float)(T0 + 0.8 * hs), kk[0], kk[1], kk[2], 0, 0,
              hs * (44.0 / 45.0), hs * (-56.0 / 15.0), hs * (32.0 / 9.0), 0, 0, 3, kk[3]);
        feval((float)(T0 + (8.0 / 9.0) * hs), kk[0], kk[1], kk[2], kk[3], 0,
              hs * (19372.0 / 6561.0), hs * (-25360.0 / 2187.0),
              hs * (64448.0 / 6561.0), hs * (-212.0 / 729.0), 0, 4, kk[4]);
        feval((float)(T0 + hs), kk[0], kk[1], kk[2], kk[3], kk[4],
              hs * (9017.0 / 3168.0), hs * (-355.0 / 33.0), hs * (46732.0 / 5247.0),
              hs * (49.0 / 176.0), hs * (-5103.0 / 18656.0), 5, kk[5]);
        combine_kernel<<<3600, 256>>>((const float4*)y, (float4*)y,
            (const float4*)kk[0], (const float4*)kk[2], (const float4*)kk[3],
            (const float4*)kk[4], (const float4*)kk[5],
            (float)(hs * (35.0 / 384.0)), (float)(hs * (500.0 / 1113.0)),
            (float)(hs * (125.0 / 192.0)), (float)(hs * (-2187.0 / 6784.0)),
            (float)(hs * (11.0 / 84.0)));
    }

    // ---- head ----
    gn225_kernel<<<BATCH * 32, 32>>>(y, t0b, out_gn_g, out_gn_b, 1);
    pool_kernel<<<2048, 256>>>(t0b, pool);
    fc_kernel<<<BATCH, 64>>>(pool, fc_w, fc_b, out);
}

// round 4
// speedup vs baseline: 1.2062x; 1.2062x over previous
#include <cuda_runtime.h>

// ---------------- sizes ----------------
#define BATCH 256
#define NY 3686400              // 256*64*15*15
#define H1N (256*64*62*62)
#define H2N (256*64*31*31)

// fused feval smem: halo 64*17*17 + weights 8ci*9*64co + stats 256
#define HALO_FLOATS (64*289)            // 18496
#define SW_FLOATS  (8*9*64)             // 4608
#define STAT_FLOATS 256
#define FEV_SMEM_FLOATS (HALO_FLOATS + SW_FLOATS + STAT_FLOATS)   // 23360
#define FEV_SMEM_BYTES (FEV_SMEM_FLOATS * 4)                      // 93440

// ---------------- scratch (device globals, no allocation) ----------------
__device__ float g_h1[H1N];
__device__ float g_h2[H2N];
__device__ float g_y[NY];
__device__ float g_t0[NY];
__device__ float g_k[6][NY];
__device__ float g_S1[64 * 225];
__device__ float g_S2[64 * 225];
__device__ float g_pool[256 * 64];

// ---------------- helpers ----------------
__inline__ __device__ float warpSum(float v) {
#pragma unroll
    for (int o = 16; o; o >>= 1) v += __shfl_xor_sync(0xffffffffu, v, o);
    return v;
}

// ---------------- conv1: 1->64, 3x3, valid, 64 -> 62 ----------------
__global__ void conv1_kernel(const float* __restrict__ x, float* __restrict__ out,
                             const float* __restrict__ w, const float* __restrict__ bias)
{
    __shared__ float sx[18][18];
    __shared__ float swt[64 * 9];
    __shared__ float sb[64];
    int b = blockIdx.y;
    int tileX = blockIdx.x & 3, tileY = blockIdx.x >> 2;
    int tx = threadIdx.x, ty = threadIdx.y;
    int tid = ty * 16 + tx;

    for (int s = tid; s < 576; s += 256) swt[s] = w[s];
    if (tid < 64) sb[tid] = bias[tid];

    const float* xb = x + (size_t)b * 64 * 64;
    int ox0 = tileX * 16, oy0 = tileY * 16;
    for (int s = tid; s < 18 * 18; s += 256) {
        int r = s / 18, c = s % 18;
        int iy = oy0 + r, ix = ox0 + c;
        sx[r][c] = (iy < 64 && ix < 64) ? xb[iy * 64 + ix] : 0.f;
    }
    __syncthreads();

    int ox = ox0 + tx, oy = oy0 + ty;
    if (ox >= 62 || oy >= 62) return;

    float v[9];
#pragma unroll
    for (int ky = 0; ky < 3; ky++)
#pragma unroll
        for (int kx = 0; kx < 3; kx++)
            v[ky * 3 + kx] = sx[ty + ky][tx + kx];

    float* ob = out + (size_t)b * 64 * 3844 + oy * 62 + ox;
#pragma unroll 4
    for (int co = 0; co < 64; co++) {
        float a = sb[co];
#pragma unroll
        for (int k = 0; k < 9; k++) a = fmaf(swt[co * 9 + k], v[k], a);
        ob[(size_t)co * 3844] = a;
    }
}

// ---------------- generic GroupNorm (big HW) ----------------
__global__ void gn_big_kernel(const float* __restrict__ in, float* __restrict__ out,
                              const float* __restrict__ gamma, const float* __restrict__ beta,
                              int HW, int relu)
{
    __shared__ float rs[8], rs2[8], stats[2];
    int bg = blockIdx.x;
    int c0 = (bg & 31) * 2;
    size_t base = (size_t)bg * 2 * HW;
    int n = 2 * HW;
    float s = 0.f, s2 = 0.f;
    for (int i = threadIdx.x; i < n; i += 256) {
        float v = in[base + i];
        s += v; s2 = fmaf(v, v, s2);
    }
    s = warpSum(s); s2 = warpSum(s2);
    int wi = threadIdx.x >> 5, lane = threadIdx.x & 31;
    if (lane == 0) { rs[wi] = s; rs2[wi] = s2; }
    __syncthreads();
    if (threadIdx.x == 0) {
        float a = 0.f, bb = 0.f;
#pragma unroll
        for (int i = 0; i < 8; i++) { a += rs[i]; bb += rs2[i]; }
        float mu = a / (float)n;
        stats[0] = mu;
        stats[1] = rsqrtf(bb / (float)n - mu * mu + 1e-5f);
    }
    __syncthreads();
    float mu = stats[0], inv = stats[1];
    float sc0 = inv * gamma[c0],     sh0 = beta[c0]     - mu * sc0;
    float sc1 = inv * gamma[c0 + 1], sh1 = beta[c0 + 1] - mu * sc1;
    for (int i = threadIdx.x; i < n; i += 256) {
        float v = in[base + i];
        float r = (i < HW) ? fmaf(v, sc0, sh0) : fmaf(v, sc1, sh1);
        if (relu) r = fmaxf(r, 0.f);
        out[base + i] = r;
    }
}

// ---------------- GroupNorm for 15x15, 1 warp per (b,g) (head only) ----------------
__global__ void gn225_kernel(const float* __restrict__ in, float* __restrict__ out,
                             const float* __restrict__ gamma, const float* __restrict__ beta,
                             int relu)
{
    int bg = blockIdx.x;
    int lane = threadIdx.x;
    size_t base = (size_t)bg * 450;
    int c0 = (bg & 31) * 2;
    float v[15];
    float s = 0.f, s2 = 0.f;
#pragma unroll
    for (int k = 0; k < 15; k++) {
        int i = k * 32 + lane;
        float xv = (i < 450) ? in[base + i] : 0.f;
        v[k] = xv;
        s += xv; s2 = fmaf(xv, xv, s2);
    }
    s = warpSum(s); s2 = warpSum(s2);
    float mu = s * (1.f / 450.f);
    float inv = rsqrtf(s2 * (1.f / 450.f) - mu * mu + 1e-5f);
    float sc0 = inv * gamma[c0],     sh0 = beta[c0]     - mu * sc0;
    float sc1 = inv * gamma[c0 + 1], sh1 = beta[c0 + 1] - mu * sc1;
#pragma unroll
    for (int k = 0; k < 15; k++) {
        int i = k * 32 + lane;
        if (i < 450) {
            float r = (i < 225) ? fmaf(v[k], sc0, sh0) : fmaf(v[k], sc1, sh1);
            if (relu) r = fmaxf(r, 0.f);
            out[base + i] = r;
        }
    }
}

// ---------------- conv 4x4 stride 2 pad 1 (64->64) ----------------
__global__ void conv4x4_kernel(const float* __restrict__ in, float* __restrict__ out,
                               const float* __restrict__ w, const float* __restrict__ bias,
                               int Hin, int Hout)
{
    __shared__ float sw[4 * 64 * 16];
    int b = blockIdx.z;
    int co0 = blockIdx.y * 4;
    int tid = threadIdx.x;
    for (int s = tid; s < 4096; s += 256) {
        int j = s >> 10;
        int ci = (s >> 4) & 63;
        int tp = s & 15;
        sw[s] = w[(((size_t)(co0 + j)) * 64 + ci) * 16 + tp];
    }
    __syncthreads();

    int p = blockIdx.x * 256 + tid;
    int HW = Hout * Hout;
    if (p >= HW) return;
    int oy = p / Hout, ox = p % Hout;

    float a0 = bias[co0], a1 = bias[co0 + 1], a2 = bias[co0 + 2], a3 = bias[co0 + 3];
    const float* inb = in + (size_t)b * 64 * Hin * Hin;

    for (int ci = 0; ci < 64; ci++) {
        const float* inc = inb + (size_t)ci * Hin * Hin;
        const float* sw0 = sw + ci * 16;
        const float* sw1 = sw + 1024 + ci * 16;
        const float* sw2 = sw + 2048 + ci * 16;
        const float* sw3 = sw + 3072 + ci * 16;
#pragma unroll
        for (int ky = 0; ky < 4; ky++) {
            int iy = oy * 2 - 1 + ky;
            if ((unsigned)iy < (unsigned)Hin) {
#pragma unroll
                for (int kx = 0; kx < 4; kx++) {
                    int ix = ox * 2 - 1 + kx;
                    if ((unsigned)ix < (unsigned)Hin) {
                        float v = __ldg(inc + iy * Hin + ix);
                        int tp = ky * 4 + kx;
                        a0 = fmaf(v, sw0[tp], a0);
                        a1 = fmaf(v, sw1[tp], a1);
                        a2 = fmaf(v, sw2[tp], a2);
                        a3 = fmaf(v, sw3[tp], a3);
                    }
                }
            }
        }
    }
    size_t ob = (((size_t)b * 64 + co0) * HW) + p;
    out[ob] = a0; out[ob + HW] = a1; out[ob + 2 * (size_t)HW] = a2; out[ob + 3 * (size_t)HW] = a3;
}

// ---------------- precompute S[co][p] ----------------
__global__ void precomp_s_kernel(const float* __restrict__ w, float* __restrict__ S)
{
    int co = blockIdx.x;
    int p = threadIdx.x;
    int y = p / 15, x = p % 15;
    float a = 0.f;
#pragma unroll
    for (int ky = 0; ky < 3; ky++) {
        int iy = y - 1 + ky;
        if ((unsigned)iy < 15u) {
#pragma unroll
            for (int kx = 0; kx < 3; kx++) {
                int ix = x - 1 + kx;
                if ((unsigned)ix < 15u) a += w[(size_t)co * 65 * 9 + ky * 3 + kx];
            }
        }
    }
    S[co * 225 + p] = a;
}

// ---------------- conv core (R2-proven): 64->64 3x3 pad1, 8-ci chunks ----------------
__device__ __forceinline__ void conv_phase(
    float* halo, float* sw, const float* __restrict__ wglob,
    int tid, int co0, const int* offs, float acc[4][15])
{
    for (int cc = 0; cc < 8; cc++) {
        __syncthreads();
        for (int s = tid; s < SW_FLOATS; s += 256) {
            int co = s & 63;
            int r = s >> 6;          // 0..71
            int k9 = r % 9;
            int ciL = r / 9;
            sw[s] = wglob[((size_t)co * 65 + (cc * 8 + ciL + 1)) * 9 + k9];
        }
        __syncthreads();

        for (int ciL = 0; ciL < 8; ciL++) {
            int sbase = (cc * 8 + ciL) * 289;
#pragma unroll
            for (int k9 = 0; k9 < 9; k9++) {
                int ky = k9 / 3, kx = k9 % 3;
                const float4 wv = *reinterpret_cast<const float4*>(&sw[(ciL * 9 + k9) * 64 + co0]);
                int tb = sbase + ky * 17 + kx;
#pragma unroll
                for (int j = 0; j < 15; j++) {
                    float v = halo[tb + offs[j]];
                    acc[0][j] = fmaf(wv.x, v, acc[0][j]);
                    acc[1][j] = fmaf(wv.y, v, acc[1][j]);
                    acc[2][j] = fmaf(wv.z, v, acc[2][j]);
                    acc[3][j] = fmaf(wv.w, v, acc[3][j]);
                }
            }
        }
    }
    __syncthreads();   // conv reads complete before halo is overwritten
}

// ---------------- fused ODE function eval ----------------
// yin = y + sum cj*kj ; GN1+relu -> conv1(+b+tS1) -> GN2+relu -> conv2(+b+tS2) -> GN3 -> kout
// grid BATCH, block 256, dyn smem 93440B
__global__ void __launch_bounds__(256, 2)
feval_kernel(const float* __restrict__ y,
             const float* __restrict__ k0, const float* __restrict__ k1,
             const float* __restrict__ k2, const float* __restrict__ k3,
             const float* __restrict__ k4,
             float c0, float c1, float c2, float c3, float c4, int nk,
             const float* __restrict__ g1, const float* __restrict__ bb1,
             const float* __restrict__ w1, const float* __restrict__ b1,
             const float* __restrict__ S1g,
             const float* __restrict__ g2, const float* __restrict__ bb2,
             const float* __restrict__ w2, const float* __restrict__ b2,
             const float* __restrict__ S2g,
             const float* __restrict__ g3, const float* __restrict__ bb3,
             float t, float* __restrict__ kout)
{
    extern __shared__ float smem[];
    float* halo  = smem;                               // 64 x 17 x 17 zero-halo
    float* sw    = smem + HALO_FLOATS;                 // weight chunk
    float* sums  = smem + HALO_FLOATS + SW_FLOATS;     // 64
    float* sumsq = sums + 64;
    float* scv   = sums + 128;
    float* shv   = sums + 192;

    int tid = threadIdx.x;
    int b = blockIdx.x;
    size_t base = (size_t)b * 14400;
    int cg = tid >> 4, pg = tid & 15;
    int co0 = cg * 4;

    // P0: zero halo
    float4* h4 = (float4*)halo;
    for (int i = tid; i < HALO_FLOATS / 4; i += 256) h4[i] = make_float4(0.f, 0.f, 0.f, 0.f);
    __syncthreads();

    // P1: combine prologue + GN1 + relu into halo. ch = tid>>2, q = tid&3
    {
        int ch = tid >> 2, q = tid & 3;
        float s = 0.f, s2 = 0.f;
        for (int j = q; j < 225; j += 4) {
            size_t idx = base + ch * 225 + j;
            float v = y[idx];
            if (nk > 0) v = fmaf(c0, k0[idx], v);
            if (nk > 1) v = fmaf(c1, k1[idx], v);
            if (nk > 2) v = fmaf(c2, k2[idx], v);
            if (nk > 3) v = fmaf(c3, k3[idx], v);
            if (nk > 4) v = fmaf(c4, k4[idx], v);
            halo[ch * 289 + (j / 15 + 1) * 17 + (j % 15) + 1] = v;
            s += v; s2 = fmaf(v, v, s2);
        }
        s  += __shfl_xor_sync(0xffffffffu, s, 1);
        s  += __shfl_xor_sync(0xffffffffu, s, 2);
        s2 += __shfl_xor_sync(0xffffffffu, s2, 1);
        s2 += __shfl_xor_sync(0xffffffffu, s2, 2);
        if (q == 0) { sums[ch] = s; sumsq[ch] = s2; }
        __syncthreads();
        if (tid < 32) {
            int ca = 2 * tid, cb = ca + 1;
            float mu = (sums[ca] + sums[cb]) * (1.f / 450.f);
            float var = (sumsq[ca] + sumsq[cb]) * (1.f / 450.f) - mu * mu;
            float inv = rsqrtf(var + 1e-5f);
            float sa = inv * g1[ca], sb2 = inv * g1[cb];
            scv[ca] = sa; shv[ca] = bb1[ca] - mu * sa;
            scv[cb] = sb2; shv[cb] = bb1[cb] - mu * sb2;
        }
        __syncthreads();
        float sc = scv[ch], sh = shv[ch];
        for (int j = q; j < 225; j += 4) {
            int hi = ch * 289 + (j / 15 + 1) * 17 + (j % 15) + 1;
            halo[hi] = fmaxf(fmaf(halo[hi], sc, sh), 0.f);
        }
    }
    // conv_phase leading sync orders halo writes before reads

    // pixel offsets for this thread (p = 16j + pg)
    int offs[15];
#pragma unroll
    for (int j = 0; j < 15; j++) {
        int p = 16 * j + pg;
        if (p >= 225) p = 0;    // dummy; masked out later
        offs[j] = (p / 15) * 17 + (p % 15);
    }

    float acc[4][15];

    // ---- conv1 ----
#pragma unroll
    for (int a = 0; a < 4; a++)
#pragma unroll
        for (int j = 0; j < 15; j++) acc[a][j] = 0.f;
    conv_phase(halo, sw, w1, tid, co0, offs, acc);

    // ---- bias + t*S1 + GN2 + relu -> halo ----
    {
        float s[4] = {0.f, 0.f, 0.f, 0.f}, s2[4] = {0.f, 0.f, 0.f, 0.f};
#pragma unroll
        for (int a = 0; a < 4; a++) {
            float bv = b1[co0 + a];
#pragma unroll
            for (int j = 0; j < 15; j++) {
                int p = 16 * j + pg;
                if (p < 225) {
                    float v = acc[a][j] + bv + t * __ldg(&S1g[(co0 + a) * 225 + p]);
                    acc[a][j] = v;
                    s[a] += v; s2[a] = fmaf(v, v, s2[a]);
                }
            }
        }
#pragma unroll
        for (int a = 0; a < 4; a++) {
#pragma unroll
            for (int o = 8; o; o >>= 1) {
                s[a]  += __shfl_xor_sync(0xffffffffu, s[a], o);
                s2[a] += __shfl_xor_sync(0xffffffffu, s2[a], o);
            }
        }
        if (pg == 0) {
#pragma unroll
            for (int a = 0; a < 4; a++) { sums[co0 + a] = s[a]; sumsq[co0 + a] = s2[a]; }
        }
        __syncthreads();
        if (tid < 32) {
            int ca = 2 * tid, cb = ca + 1;
            float mu = (sums[ca] + sums[cb]) * (1.f / 450.f);
            float var = (sumsq[ca] + sumsq[cb]) * (1.f / 450.f) - mu * mu;
            float inv = rsqrtf(var + 1e-5f);
            float sa = inv * g2[ca], sb2 = inv * g2[cb];
            scv[ca] = sa; shv[ca] = bb2[ca] - mu * sa;
            scv[cb] = sb2; shv[cb] = bb2[cb] - mu * sb2;
        }
        __syncthreads();
#pragma unroll
        for (int a = 0; a < 4; a++) {
            float sc = scv[co0 + a], sh = shv[co0 + a];
#pragma unroll
            for (int j = 0; j < 15; j++) {
                int p = 16 * j + pg;
                if (p < 225)
                    halo[(co0 + a) * 289 + offs[j] + 18] = fmaxf(fmaf(acc[a][j], sc, sh), 0.f);
            }
        }
    }

    // ---- conv2 ----
#pragma unroll
    for (int a = 0; a < 4; a++)
#pragma unroll
        for (int j = 0; j < 15; j++) acc[a][j] = 0.f;
    conv_phase(halo, sw, w2, tid, co0, offs, acc);

    // ---- bias + t*S2 + GN3 (no relu) -> kout ----
    {
        float s[4] = {0.f, 0.f, 0.f, 0.f}, s2[4] = {0.f, 0.f, 0.f, 0.f};
#pragma unroll
        for (int a = 0; a < 4; a++) {
            float bv = b2[co0 + a];
#pragma unroll
            for (int j = 0; j < 15; j++) {
                int p = 16 * j + pg;
                if (p < 225) {
                    float v = acc[a][j] + bv + t * __ldg(&S2g[(co0 + a) * 225 + p]);
                    acc[a][j] = v;
                    s[a] += v; s2[a] = fmaf(v, v, s2[a]);
                }
            }
        }
#pragma unroll
        for (int a = 0; a < 4; a++) {
#pragma unroll
            for (int o = 8; o; o >>= 1) {
                s[a]  += __shfl_xor_sync(0xffffffffu, s[a], o);
                s2[a] += __shfl_xor_sync(0xffffffffu, s2[a], o);
            }
        }
        if (pg == 0) {
#pragma unroll
            for (int a = 0; a < 4; a++) { sums[co0 + a] = s[a]; sumsq[co0 + a] = s2[a]; }
        }
        __syncthreads();
        if (tid < 32) {
            int ca = 2 * tid, cb = ca + 1;
            float mu = (sums[ca] + sums[cb]) * (1.f / 450.f);
            float var = (sumsq[ca] + sumsq[cb]) * (1.f / 450.f) - mu * mu;
            float inv = rsqrtf(var + 1e-5f);
            float sa = inv * g3[ca], sb2 = inv * g3[cb];
            scv[ca] = sa; shv[ca] = bb3[ca] - mu * sa;
            scv[cb] = sb2; shv[cb] = bb3[cb] - mu * sb2;
        }
        __syncthreads();
#pragma unroll
        for (int a = 0; a < 4; a++) {
            float sc = scv[co0 + a], sh = shv[co0 + a];
#pragma unroll
            for (int j = 0; j < 15; j++) {
                int p = 16 * j + pg;
                if (p < 225)
                    kout[base + (co0 + a) * 225 + p] = fmaf(acc[a][j], sc, sh);
            }
        }
    }
}

// ---------------- dopri final combine (per step): y += sum cj*kj ----------------
__global__ void combine_kernel(const float4* __restrict__ y, float4* __restrict__ dst,
                               const float4* __restrict__ p0, const float4* __restrict__ p1,
                               const float4* __restrict__ p2, const float4* __restrict__ p3,
                               const float4* __restrict__ p4,
                               float c0, float c1, float c2, float c3, float c4)
{
    int i = blockIdx.x * 256 + threadIdx.x;
    float4 a = y[i];
    float4 t;
    t = p0[i]; a.x = fmaf(c0, t.x, a.x); a.y = fmaf(c0, t.y, a.y); a.z = fmaf(c0, t.z, a.z); a.w = fmaf(c0, t.w, a.w);
    t = p1[i]; a.x = fmaf(c1, t.x, a.x); a.y = fmaf(c1, t.y, a.y); a.z = fmaf(c1, t.z, a.z); a.w = fmaf(c1, t.w, a.w);
    t = p2[i]; a.x = fmaf(c2, t.x, a.x); a.y = fmaf(c2, t.y, a.y); a.z = fmaf(c2, t.z, a.z); a.w = fmaf(c2, t.w, a.w);
    t = p3[i]; a.x = fmaf(c3, t.x, a.x); a.y = fmaf(c3, t.y, a.y); a.z = fmaf(c3, t.z, a.z); a.w = fmaf(c3, t.w, a.w);
    t = p4[i]; a.x = fmaf(c4, t.x, a.x); a.y = fmaf(c4, t.y, a.y); a.z = fmaf(c4, t.z, a.z); a.w = fmaf(c4, t.w, a.w);
    dst[i] = a;
}

// ---------------- global mean pool ----------------
__global__ void pool_kernel(const float* __restrict__ in, float* __restrict__ out)
{
    int gw = (blockIdx.x * 256 + threadIdx.x) >> 5;
    int lane = threadIdx.x & 31;
    const float* p = in + (size_t)gw * 225;
    float s = 0.f;
    for (int i = lane; i < 225; i += 32) s += p[i];
    s = warpSum(s);
    if (lane == 0) out[gw] = s * (1.f / 225.f);
}

// ---------------- FC 64->10 ----------------
__global__ void fc_kernel(const float* __restrict__ pool, const float* __restrict__ w,
                          const float* __restrict__ bias, float* __restrict__ out)
{
    __shared__ float sp[64];
    int b = blockIdx.x;
    sp[threadIdx.x] = pool[b * 64 + threadIdx.x];
    __syncthreads();
    if (threadIdx.x < 10) {
        float a = bias[threadIdx.x];
#pragma unroll
        for (int c = 0; c < 64; c++) a = fmaf(sp[c], __ldg(&w[threadIdx.x * 64 + c]), a);
        out[b * 10 + threadIdx.x] = a;
    }
}

// ---------------- launch ----------------
extern "C" void kernel_launch(void* const* d_in, const int* in_sizes, int n_in,
                              void* d_out, int out_size)
{
    const float* x        = (const float*)d_in[0];
    const float* conv1_w  = (const float*)d_in[1];
    const float* conv1_b  = (const float*)d_in[2];
    const float* gn1_g    = (const float*)d_in[3];
    const float* gn1_b    = (const float*)d_in[4];
    const float* conv2_w  = (const float*)d_in[5];
    const float* conv2_b  = (const float*)d_in[6];
    const float* gn2_g    = (const float*)d_in[7];
    const float* gn2_b    = (const float*)d_in[8];
    const float* conv3_w  = (const float*)d_in[9];
    const float* conv3_b  = (const float*)d_in[10];
    const float* f_gn1_g  = (const float*)d_in[11];
    const float* f_gn1_b  = (const float*)d_in[12];
    const float* f_conv1_w= (const float*)d_in[13];
    const float* f_conv1_b= (const float*)d_in[14];
    const float* f_gn2_g  = (const float*)d_in[15];
    const float* f_gn2_b  = (const float*)d_in[16];
    const float* f_conv2_w= (const float*)d_in[17];
    const float* f_conv2_b= (const float*)d_in[18];
    const float* f_gn3_g  = (const float*)d_in[19];
    const float* f_gn3_b  = (const float*)d_in[20];
    const float* out_gn_g = (const float*)d_in[21];
    const float* out_gn_b = (const float*)d_in[22];
    const float* fc_w     = (const float*)d_in[23];
    const float* fc_b     = (const float*)d_in[24];
    float* out = (float*)d_out;

    float *h1, *h2, *y, *t0b, *kbase, *S1, *S2, *pool;
    cudaGetSymbolAddress((void**)&h1, g_h1);
    cudaGetSymbolAddress((void**)&h2, g_h2);
    cudaGetSymbolAddress((void**)&y, g_y);
    cudaGetSymbolAddress((void**)&t0b, g_t0);
    cudaGetSymbolAddress((void**)&kbase, g_k);
    cudaGetSymbolAddress((void**)&S1, g_S1);
    cudaGetSymbolAddress((void**)&S2, g_S2);
    cudaGetSymbolAddress((void**)&pool, g_pool);
    float* kk[6];
    for (int i = 0; i < 6; i++) kk[i] = kbase + (size_t)i * NY;

    cudaFuncSetAttribute(feval_kernel, cudaFuncAttributeMaxDynamicSharedMemorySize, FEV_SMEM_BYTES);

    // ---- downsampling ----
    conv1_kernel<<<dim3(16, BATCH), dim3(16, 16)>>>(x, h1, conv1_w, conv1_b);
    gn_big_kernel<<<BATCH * 32, 256>>>(h1, h1, gn1_g, gn1_b, 62 * 62, 1);
    conv4x4_kernel<<<dim3(4, 16, BATCH), 256>>>(h1, h2, conv2_w, conv2_b, 62, 31);
    gn_big_kernel<<<BATCH * 32, 256>>>(h2, h2, gn2_g, gn2_b, 31 * 31, 1);
    conv4x4_kernel<<<dim3(1, 16, BATCH), 256>>>(h2, y, conv3_w, conv3_b, 31, 15);

    precomp_s_kernel<<<64, 225>>>(f_conv1_w, S1);
    precomp_s_kernel<<<64, 225>>>(f_conv2_w, S2);

    auto feval = [&](float t, const float* p0, const float* p1, const float* p2,
                     const float* p3, const float* p4,
                     double c0, double c1, double c2, double c3, double c4,
                     int nk, float* kout) {
        feval_kernel<<<BATCH, 256, FEV_SMEM_BYTES>>>(
            y, p0 ? p0 : y, p1 ? p1 : y, p2 ? p2 : y, p3 ? p3 : y, p4 ? p4 : y,
            (float)c0, (float)c1, (float)c2, (float)c3, (float)c4, nk,
            f_gn1_g, f_gn1_b, f_conv1_w, f_conv1_b, S1,
            f_gn2_g, f_gn2_b, f_conv2_w, f_conv2_b, S2,
            f_gn3_g, f_gn3_b, t, kout);
    };

    const double hs = 1.0 / 8.0;
    for (int st = 0; st < 8; st++) {
        double T0 = st * hs;
        feval((float)T0, 0, 0, 0, 0, 0, 0, 0, 0, 0, 0, 0, kk[0]);
        feval((float)(T0 + hs / 5.0), kk[0], 0, 0, 0, 0,
              hs * (1.0 / 5.0), 0, 0, 0, 0, 1, kk[1]);
        feval((float)(T0 + 0.3 * hs), kk[0], kk[1], 0, 0, 0,
              hs * (3.0 / 40.0), hs * (9.0 / 40.0), 0, 0, 0, 2, kk[2]);
        feval((float)(T0 + 0.8 * hs), kk[0], kk[1], kk[2], 0, 0,
              hs * (44.0 / 45.0), hs * (-56.0 / 15.0), hs * (32.0 / 9.0), 0, 0, 3, kk[3]);
        feval((float)(T0 + (8.0 / 9.0) * hs), kk[0], kk[1], kk[2], kk[3], 0,
              hs * (19372.0 / 6561.0), hs * (-25360.0 / 2187.0),
              hs * (64448.0 / 6561.0), hs * (-212.0 / 729.0), 0, 4, kk[4]);
        feval((float)(T0 + hs), kk[0], kk[1], kk[2], kk[3], kk[4],
              hs * (9017.0 / 3168.0), hs * (-355.0 / 33.0), hs * (46732.0 / 5247.0),
              hs * (49.0 / 176.0), hs * (-5103.0 / 18656.0), 5, kk[5]);
        combine_kernel<<<3600, 256>>>((const float4*)y, (float4*)y,
            (const float4*)kk[0], (const float4*)kk[2], (const float4*)kk[3],
            (const float4*)kk[4], (const float4*)kk[5],
            (float)(hs * (35.0 / 384.0)), (float)(hs * (500.0 / 1113.0)),
            (float)(hs * (125.0 / 192.0)), (float)(hs * (-2187.0 / 6784.0)),
            (float)(hs * (11.0 / 84.0)));
    }

    // ---- head ----
    gn225_kernel<<<BATCH * 32, 32>>>(y, t0b, out_gn_g, out_gn_b, 1);
    pool_kernel<<<2048, 256>>>(t0b, pool);
    fc_kernel<<<BATCH, 64>>>(pool, fc_w, fc_b, out);
}

// round 6
// speedup vs baseline: 2.2496x; 1.8651x over previous
#include <cuda_runtime.h>
#include <cuda_bf16.h>
#include <cstdint>

// ---------------- sizes ----------------
#define BATCH 256
#define NY 3686400              // 256*64*15*15
#define H1N (256*64*62*62)
#define H2N (256*64*31*31)

// smem layout for mma conv (bytes from dynamic smem base)
#define MM_HHI 0
#define MM_HLO 39168            // halo: 306 rows x 128B
#define MM_BHI 78336            // weights: 64 rows x 128B
#define MM_BLO 86528
#define MM_SMEM_BYTES 94720

// ---------------- scratch (device globals, no allocation) ----------------
__device__ float g_h1[H1N];
__device__ float g_h2[H2N];
__device__ float g_y[NY];
__device__ float g_ytmp[NY];
__device__ float g_t0[NY];
__device__ float g_t1[NY];
__device__ float g_t2[NY];
__device__ float g_k[6][NY];
__device__ float g_S1[64 * 225];
__device__ float g_S2[64 * 225];
__device__ float g_pool[256 * 64];
__device__ __nv_bfloat16 g_w1hi[9 * 4096];
__device__ __nv_bfloat16 g_w1lo[9 * 4096];
__device__ __nv_bfloat16 g_w2hi[9 * 4096];
__device__ __nv_bfloat16 g_w2lo[9 * 4096];

// ---------------- helpers ----------------
__inline__ __device__ float warpSum(float v) {
#pragma unroll
    for (int o = 16; o; o >>= 1) v += __shfl_xor_sync(0xffffffffu, v, o);
    return v;
}

__device__ __forceinline__ uint32_t smem_u32(const void* p) {
    uint32_t a;
    asm("{ .reg .u64 tmp; cvta.to.shared.u64 tmp, %1; cvt.u32.u64 %0, tmp; }"
        : "=r"(a) : "l"(p));
    return a;
}
__device__ __forceinline__ void ldsm4(uint32_t* r, uint32_t addr) {
    asm volatile("ldmatrix.sync.aligned.m8n8.x4.shared.b16 {%0,%1,%2,%3}, [%4];"
        : "=r"(r[0]), "=r"(r[1]), "=r"(r[2]), "=r"(r[3]) : "r"(addr));
}
__device__ __forceinline__ void ldsm2(uint32_t* r, uint32_t addr) {
    asm volatile("ldmatrix.sync.aligned.m8n8.x2.shared.b16 {%0,%1}, [%2];"
        : "=r"(r[0]), "=r"(r[1]) : "r"(addr));
}
__device__ __forceinline__ void mma_bf16(float* c, const uint32_t* a, const uint32_t* b) {
    asm volatile("mma.sync.aligned.m16n8k16.row.col.f32.bf16.bf16.f32 "
        "{%0,%1,%2,%3}, {%4,%5,%6,%7}, {%8,%9}, {%0,%1,%2,%3};"
        : "+f"(c[0]), "+f"(c[1]), "+f"(c[2]), "+f"(c[3])
        : "r"(a[0]), "r"(a[1]), "r"(a[2]), "r"(a[3]), "r"(b[0]), "r"(b[1]));
}

// ---------------- conv1: 1->64, 3x3, valid ----------------
__global__ void conv1_kernel(const float* __restrict__ x, float* __restrict__ out,
                             const float* __restrict__ w, const float* __restrict__ bias)
{
    __shared__ float sx[18][18];
    __shared__ float swt[64 * 9];
    __shared__ float sb[64];
    int b = blockIdx.y;
    int tileX = blockIdx.x & 3, tileY = blockIdx.x >> 2;
    int tx = threadIdx.x, ty = threadIdx.y;
    int tid = ty * 16 + tx;

    for (int s = tid; s < 576; s += 256) swt[s] = w[s];
    if (tid < 64) sb[tid] = bias[tid];

    const float* xb = x + (size_t)b * 64 * 64;
    int ox0 = tileX * 16, oy0 = tileY * 16;
    for (int s = tid; s < 18 * 18; s += 256) {
        int r = s / 18, c = s % 18;
        int iy = oy0 + r, ix = ox0 + c;
        sx[r][c] = (iy < 64 && ix < 64) ? xb[iy * 64 + ix] : 0.f;
    }
    __syncthreads();

    int ox = ox0 + tx, oy = oy0 + ty;
    if (ox >= 62 || oy >= 62) return;

    float v[9];
#pragma unroll
    for (int ky = 0; ky < 3; ky++)
#pragma unroll
        for (int kx = 0; kx < 3; kx++)
            v[ky * 3 + kx] = sx[ty + ky][tx + kx];

    float* ob = out + (size_t)b * 64 * 3844 + oy * 62 + ox;
#pragma unroll 4
    for (int co = 0; co < 64; co++) {
        float a = sb[co];
#pragma unroll
        for (int k = 0; k < 9; k++) a = fmaf(swt[co * 9 + k], v[k], a);
        ob[(size_t)co * 3844] = a;
    }
}

// ---------------- generic GroupNorm (big HW) ----------------
__global__ void gn_big_kernel(const float* __restrict__ in, float* __restrict__ out,
                              const float* __restrict__ gamma, const float* __restrict__ beta,
                              int HW, int relu)
{
    __shared__ float rs[8], rs2[8], stats[2];
    int bg = blockIdx.x;
    int c0 = (bg & 31) * 2;
    size_t base = (size_t)bg * 2 * HW;
    int n = 2 * HW;
    float s = 0.f, s2 = 0.f;
    for (int i = threadIdx.x; i < n; i += 256) {
        float v = in[base + i];
        s += v; s2 = fmaf(v, v, s2);
    }
    s = warpSum(s); s2 = warpSum(s2);
    int wi = threadIdx.x >> 5, lane = threadIdx.x & 31;
    if (lane == 0) { rs[wi] = s; rs2[wi] = s2; }
    __syncthreads();
    if (threadIdx.x == 0) {
        float a = 0.f, bb = 0.f;
#pragma unroll
        for (int i = 0; i < 8; i++) { a += rs[i]; bb += rs2[i]; }
        float mu = a / (float)n;
        stats[0] = mu;
        stats[1] = rsqrtf(bb / (float)n - mu * mu + 1e-5f);
    }
    __syncthreads();
    float mu = stats[0], inv = stats[1];
    float sc0 = inv * gamma[c0],     sh0 = beta[c0]     - mu * sc0;
    float sc1 = inv * gamma[c0 + 1], sh1 = beta[c0 + 1] - mu * sc1;
    for (int i = threadIdx.x; i < n; i += 256) {
        float v = in[base + i];
        float r = (i < HW) ? fmaf(v, sc0, sh0) : fmaf(v, sc1, sh1);
        if (relu) r = fmaxf(r, 0.f);
        out[base + i] = r;
    }
}

// ---------------- GroupNorm for 15x15, 1 warp per (b,g) ----------------
__global__ void gn225_kernel(const float* __restrict__ in, float* __restrict__ out,
                             const float* __restrict__ gamma, const float* __restrict__ beta,
                             int relu)
{
    int bg = blockIdx.x;
    int lane = threadIdx.x;
    size_t base = (size_t)bg * 450;
    int c0 = (bg & 31) * 2;
    float v[15];
    float s = 0.f, s2 = 0.f;
#pragma unroll
    for (int k = 0; k < 15; k++) {
        int i = k * 32 + lane;
        float xv = (i < 450) ? in[base + i] : 0.f;
        v[k] = xv;
        s += xv; s2 = fmaf(xv, xv, s2);
    }
    s = warpSum(s); s2 = warpSum(s2);
    float mu = s * (1.f / 450.f);
    float inv = rsqrtf(s2 * (1.f / 450.f) - mu * mu + 1e-5f);
    float sc0 = inv * gamma[c0],     sh0 = beta[c0]     - mu * sc0;
    float sc1 = inv * gamma[c0 + 1], sh1 = beta[c0 + 1] - mu * sc1;
#pragma unroll
    for (int k = 0; k < 15; k++) {
        int i = k * 32 + lane;
        if (i < 450) {
            float r = (i < 225) ? fmaf(v[k], sc0, sh0) : fmaf(v[k], sc1, sh1);
            if (relu) r = fmaxf(r, 0.f);
            out[base + i] = r;
        }
    }
}

// ---------------- conv 4x4 stride 2 pad 1 (64->64) ----------------
__global__ void conv4x4_kernel(const float* __restrict__ in, float* __restrict__ out,
                               const float* __restrict__ w, const float* __restrict__ bias,
                               int Hin, int Hout)
{
    __shared__ float sw[4 * 64 * 16];
    int b = blockIdx.z;
    int co0 = blockIdx.y * 4;
    int tid = threadIdx.x;
    for (int s = tid; s < 4096; s += 256) {
        int j = s >> 10;
        int ci = (s >> 4) & 63;
        int tp = s & 15;
        sw[s] = w[(((size_t)(co0 + j)) * 64 + ci) * 16 + tp];
    }
    __syncthreads();

    int p = blockIdx.x * 256 + tid;
    int HW = Hout * Hout;
    if (p >= HW) return;
    int oy = p / Hout, ox = p % Hout;

    float a0 = bias[co0], a1 = bias[co0 + 1], a2 = bias[co0 + 2], a3 = bias[co0 + 3];
    const float* inb = in + (size_t)b * 64 * Hin * Hin;

    for (int ci = 0; ci < 64; ci++) {
        const float* inc = inb + (size_t)ci * Hin * Hin;
        const float* sw0 = sw + ci * 16;
        const float* sw1 = sw + 1024 + ci * 16;
        const float* sw2 = sw + 2048 + ci * 16;
        const float* sw3 = sw + 3072 + ci * 16;
#pragma unroll
        for (int ky = 0; ky < 4; ky++) {
            int iy = oy * 2 - 1 + ky;
            if ((unsigned)iy < (unsigned)Hin) {
#pragma unroll
                for (int kx = 0; kx < 4; kx++) {
                    int ix = ox * 2 - 1 + kx;
                    if ((unsigned)ix < (unsigned)Hin) {
                        float v = __ldg(inc + iy * Hin + ix);
                        int tp = ky * 4 + kx;
                        a0 = fmaf(v, sw0[tp], a0);
                        a1 = fmaf(v, sw1[tp], a1);
                        a2 = fmaf(v, sw2[tp], a2);
                        a3 = fmaf(v, sw3[tp], a3);
                    }
                }
            }
        }
    }
    size_t ob = (((size_t)b * 64 + co0) * HW) + p;
    out[ob] = a0; out[ob + HW] = a1; out[ob + 2 * (size_t)HW] = a2; out[ob + 3 * (size_t)HW] = a3;
}

// ---------------- precompute S[co][p] ----------------
__global__ void precomp_s_kernel(const float* __restrict__ w, float* __restrict__ S)
{
    int co = blockIdx.x;
    int p = threadIdx.x;
    int y = p / 15, x = p % 15;
    float a = 0.f;
#pragma unroll
    for (int ky = 0; ky < 3; ky++) {
        int iy = y - 1 + ky;
        if ((unsigned)iy < 15u) {
#pragma unroll
            for (int kx = 0; kx < 3; kx++) {
                int ix = x - 1 + kx;
                if ((unsigned)ix < 15u) a += w[(size_t)co * 65 * 9 + ky * 3 + kx];
            }
        }
    }
    S[co * 225 + p] = a;
}

// ---------------- precompute swizzled bf16 hi/lo weights per tap ----------------
// layout: [tap][co][swz(ci)] bf16, row = co (128B), 16B chunk ci>>3 XOR (co&7)
__global__ void precomp_w_kernel(const float* __restrict__ w,
                                 __nv_bfloat16* __restrict__ hi,
                                 __nv_bfloat16* __restrict__ lo)
{
    int tap = blockIdx.x;
    for (int s = threadIdx.x; s < 4096; s += 256) {
        int co = s >> 6, ci = s & 63;
        float v = w[((size_t)co * 65 + ci + 1) * 9 + tap];
        __nv_bfloat16 h = __float2bfloat16(v);
        int pos = tap * 4096 + co * 64 + ((((ci >> 3) ^ (co & 7)) << 3) + (ci & 7));
        hi[pos] = h;
        lo[pos] = __float2bfloat16(v - __bfloat162float(h));
    }
}

// ---------------- ODE conv via legacy mma.sync (bf16x3) ----------------
// out[b][co][p] = conv3x3(in)[co][p] + bias[co] + t*S[co][p]
// grid BATCH, block 256 (8 warps), dyn smem MM_SMEM_BYTES
__global__ void __launch_bounds__(256, 2)
ode_conv_mma(const float* __restrict__ in, float* __restrict__ out,
             const __nv_bfloat16* __restrict__ whi, const __nv_bfloat16* __restrict__ wlo,
             const float* __restrict__ bias, const float* __restrict__ S, float t)
{
    extern __shared__ __align__(128) char smem[];
    uint32_t smBase = smem_u32(smem);
    const uint32_t HHIa = smBase + MM_HHI;
    const uint32_t BHIa = smBase + MM_BHI;

    int tid = threadIdx.x;
    int wid = tid >> 5, lane = tid & 31;
    int b = blockIdx.x;
    size_t base = (size_t)b * 14400;

    // zero both halos (78336 B = 4896 uint4)
    {
        uint4 z = make_uint4(0u, 0u, 0u, 0u);
        uint4* h4 = (uint4*)smem;
        for (int i = tid; i < 4896; i += 256) h4[i] = z;
    }
    __syncthreads();
    // fill halo hi/lo: row r = (iy+1)*18 + ix+1, channel-last, swizzled 16B chunks
    {
        __nv_bfloat16* hh = (__nv_bfloat16*)(smem + MM_HHI);
        __nv_bfloat16* hl = (__nv_bfloat16*)(smem + MM_HLO);
        for (int s = tid; s < 14400; s += 256) {
            int ci = s / 225, p = s % 225;
            float v = in[base + s];
            __nv_bfloat16 h = __float2bfloat16(v);
            int r = (p / 15 + 1) * 18 + (p % 15) + 1;
            int off = r * 64 + ((((ci >> 3) ^ (r & 7)) << 3) + (ci & 7));
            hh[off] = h;
            hl[off] = __float2bfloat16(v - __bfloat162float(h));
        }
    }

    float acc[2][8][4];
#pragma unroll
    for (int m = 0; m < 2; m++)
#pragma unroll
        for (int n = 0; n < 8; n++)
#pragma unroll
            for (int v = 0; v < 4; v++) acc[m][n][v] = 0.f;

    for (int tap = 0; tap < 9; tap++) {
        __syncthreads();   // also covers initial halo fill on tap==0
        {
            const uint4* gh = (const uint4*)(whi + tap * 4096);
            const uint4* gl = (const uint4*)(wlo + tap * 4096);
            uint4* sh = (uint4*)(smem + MM_BHI);
            uint4* sl = (uint4*)(smem + MM_BLO);
            for (int i = tid; i < 512; i += 256) { sh[i] = gh[i]; sl[i] = gl[i]; }
        }
        __syncthreads();

        int dd = (tap / 3) * 18 + (tap % 3);
        for (int kt = 0; kt < 4; kt++) {
            // B fragments for all 8 n-tiles (hi & lo)
            uint32_t bh[8][2], bl[8][2];
            int nrow = lane & 7;
            int bphys = ((kt * 2 + ((lane >> 3) & 1)) ^ nrow) * 16;
#pragma unroll
            for (int nt = 0; nt < 8; nt++) {
                uint32_t ab = BHIa + (nt * 8 + nrow) * 128 + bphys;
                ldsm2(bh[nt], ab);
                ldsm2(bl[nt], ab + (MM_BLO - MM_BHI));
            }
#pragma unroll
            for (int mti = 0; mti < 2; mti++) {
                int mtile = wid + mti * 8;   // mtile == output row y
                if (mtile < 15) {
                    int r = mtile * 18 + (lane & 15) + dd;
                    int aphys = ((kt * 2 + (lane >> 4)) ^ (r & 7)) * 16;
                    uint32_t aa = HHIa + r * 128 + aphys;
                    uint32_t ah[4], al[4];
                    ldsm4(ah, aa);
                    ldsm4(al, aa + (MM_HLO - MM_HHI));
#pragma unroll
                    for (int nt = 0; nt < 8; nt++) {
                        mma_bf16(acc[mti][nt], ah, bh[nt]);
                        mma_bf16(acc[mti][nt], ah, bl[nt]);
                        mma_bf16(acc[mti][nt], al, bh[nt]);
                    }
                }
            }
        }
    }

    // epilogue: D frag (m16n8): rows lane>>2 and +8 (x coord), cols (lane&3)*2,+1 (co in tile)
    int row0 = lane >> 2;
    int colb = (lane & 3) * 2;
#pragma unroll
    for (int mti = 0; mti < 2; mti++) {
        int mtile = wid + mti * 8;
        if (mtile >= 15) continue;
        int p0 = mtile * 15 + row0;            // x = row0 (0..7, always valid)
        int p1 = mtile * 15 + row0 + 8;        // x = row0+8 (valid if <15)
        bool v1 = (row0 + 8) < 15;
#pragma unroll
        for (int nt = 0; nt < 8; nt++) {
            int co = nt * 8 + colb;
            float b0 = __ldg(&bias[co]), b1 = __ldg(&bias[co + 1]);
            float* oc0 = out + base + (size_t)co * 225;
            float* oc1 = oc0 + 225;
            oc0[p0] = acc[mti][nt][0] + b0 + t * __ldg(&S[co * 225 + p0]);
            oc1[p0] = acc[mti][nt][1] + b1 + t * __ldg(&S[(co + 1) * 225 + p0]);
            if (v1) {
                oc0[p1] = acc[mti][nt][2] + b0 + t * __ldg(&S[co * 225 + p1]);
                oc1[p1] = acc[mti][nt][3] + b1 + t * __ldg(&S[(co + 1) * 225 + p1]);
            }
        }
    }
}

// ---------------- dopri combine: dst = y + sum_j c_j * k_j ----------------
__global__ void combine_kernel(const float4* __restrict__ y, float4* __restrict__ dst,
                               const float4* __restrict__ p0, const float4* __restrict__ p1,
                               const float4* __restrict__ p2, const float4* __restrict__ p3,
                               const float4* __restrict__ p4,
                               float c0, float c1, float c2, float c3, float c4, int n)
{
    int i = blockIdx.x * 256 + threadIdx.x;
    float4 a = y[i];
    float4 t = p0[i];
    a.x = fmaf(c0, t.x, a.x); a.y = fmaf(c0, t.y, a.y); a.z = fmaf(c0, t.z, a.z); a.w = fmaf(c0, t.w, a.w);
    if (n > 1) { t = p1[i]; a.x = fmaf(c1, t.x, a.x); a.y = fmaf(c1, t.y, a.y); a.z = fmaf(c1, t.z, a.z); a.w = fmaf(c1, t.w, a.w); }
    if (n > 2) { t = p2[i]; a.x = fmaf(c2, t.x, a.x); a.y = fmaf(c2, t.y, a.y); a.z = fmaf(c2, t.z, a.z); a.w = fmaf(c2, t.w, a.w); }
    if (n > 3) { t = p3[i]; a.x = fmaf(c3, t.x, a.x); a.y = fmaf(c3, t.y, a.y); a.z = fmaf(c3, t.z, a.z); a.w = fmaf(c3, t.w, a.w); }
    if (n > 4) { t = p4[i]; a.x = fmaf(c4, t.x, a.x); a.y = fmaf(c4, t.y, a.y); a.z = fmaf(c4, t.z, a.z); a.w = fmaf(c4, t.w, a.w); }
    dst[i] = a;
}

// ---------------- global mean pool ----------------
__global__ void pool_kernel(const float* __restrict__ in, float* __restrict__ out)
{
    int gw = (blockIdx.x * 256 + threadIdx.x) >> 5;
    int lane = threadIdx.x & 31;
    const float* p = in + (size_t)gw * 225;
    float s = 0.f;
    for (int i = lane; i < 225; i += 32) s += p[i];
    s = warpSum(s);
    if (lane == 0) out[gw] = s * (1.f / 225.f);
}

// ---------------- FC 64->10 ----------------
__global__ void fc_kernel(const float* __restrict__ pool, const float* __restrict__ w,
                          const float* __restrict__ bias, float* __restrict__ out)
{
    __shared__ float sp[64];
    int b = blockIdx.x;
    sp[threadIdx.x] = pool[b * 64 + threadIdx.x];
    __syncthreads();
    if (threadIdx.x < 10) {
        float a = bias[threadIdx.x];
#pragma unroll
        for (int c = 0; c < 64; c++) a = fmaf(sp[c], __ldg(&w[threadIdx.x * 64 + c]), a);
        out[b * 10 + threadIdx.x] = a;
    }
}

// ---------------- launch ----------------
extern "C" void kernel_launch(void* const* d_in, const int* in_sizes, int n_in,
                              void* d_out, int out_size)
{
    const float* x        = (const float*)d_in[0];
    const float* conv1_w  = (const float*)d_in[1];
    const float* conv1_b  = (const float*)d_in[2];
    const float* gn1_g    = (const float*)d_in[3];
    const float* gn1_b    = (const float*)d_in[4];
    const float* conv2_w  = (const float*)d_in[5];
    const float* conv2_b  = (const float*)d_in[6];
    const float* gn2_g    = (const float*)d_in[7];
    const float* gn2_b    = (const float*)d_in[8];
    const float* conv3_w  = (const float*)d_in[9];
    const float* conv3_b  = (const float*)d_in[10];
    const float* f_gn1_g  = (const float*)d_in[11];
    const float* f_gn1_b  = (const float*)d_in[12];
    const float* f_conv1_w= (const float*)d_in[13];
    const float* f_conv1_b= (const float*)d_in[14];
    const float* f_gn2_g  = (const float*)d_in[15];
    const float* f_gn2_b  = (const float*)d_in[16];
    const float* f_conv2_w= (const float*)d_in[17];
    const float* f_conv2_b= (const float*)d_in[18];
    const float* f_gn3_g  = (const float*)d_in[19];
    const float* f_gn3_b  = (const float*)d_in[20];
    const float* out_gn_g = (const float*)d_in[21];
    const float* out_gn_b = (const float*)d_in[22];
    const float* fc_w     = (const float*)d_in[23];
    const float* fc_b     = (const float*)d_in[24];
    float* out = (float*)d_out;

    float *h1, *h2, *y, *ytmp, *t0b, *t1b, *t2b, *kbase, *S1, *S2, *pool;
    __nv_bfloat16 *w1hi, *w1lo, *w2hi, *w2lo;
    cudaGetSymbolAddress((void**)&h1, g_h1);
    cudaGetSymbolAddress((void**)&h2, g_h2);
    cudaGetSymbolAddress((void**)&y, g_y);
    cudaGetSymbolAddress((void**)&ytmp, g_ytmp);
    cudaGetSymbolAddress((void**)&t0b, g_t0);
    cudaGetSymbolAddress((void**)&t1b, g_t1);
    cudaGetSymbolAddress((void**)&t2b, g_t2);
    cudaGetSymbolAddress((void**)&kbase, g_k);
    cudaGetSymbolAddress((void**)&S1, g_S1);
    cudaGetSymbolAddress((void**)&S2, g_S2);
    cudaGetSymbolAddress((void**)&pool, g_pool);
    cudaGetSymbolAddress((void**)&w1hi, g_w1hi);
    cudaGetSymbolAddress((void**)&w1lo, g_w1lo);
    cudaGetSymbolAddress((void**)&w2hi, g_w2hi);
    cudaGetSymbolAddress((void**)&w2lo, g_w2lo);
    float* kk[6];
    for (int i = 0; i < 6; i++) kk[i] = kbase + (size_t)i * NY;

    cudaFuncSetAttribute(ode_conv_mma, cudaFuncAttributeMaxDynamicSharedMemorySize, MM_SMEM_BYTES);

    // ---- downsampling ----
    conv1_kernel<<<dim3(16, BATCH), dim3(16, 16)>>>(x, h1, conv1_w, conv1_b);
    gn_big_kernel<<<BATCH * 32, 256>>>(h1, h1, gn1_g, gn1_b, 62 * 62, 1);
    conv4x4_kernel<<<dim3(4, 16, BATCH), 256>>>(h1, h2, conv2_w, conv2_b, 62, 31);
    gn_big_kernel<<<BATCH * 32, 256>>>(h2, h2, gn2_g, gn2_b, 31 * 31, 1);
    conv4x4_kernel<<<dim3(1, 16, BATCH), 256>>>(h2, y, conv3_w, conv3_b, 31, 15);

    precomp_s_kernel<<<64, 225>>>(f_conv1_w, S1);
    precomp_s_kernel<<<64, 225>>>(f_conv2_w, S2);
    precomp_w_kernel<<<9, 256>>>(f_conv1_w, w1hi, w1lo);
    precomp_w_kernel<<<9, 256>>>(f_conv2_w, w2hi, w2lo);

    auto feval = [&](float t, const float* yin, float* kout) {
        gn225_kernel<<<BATCH * 32, 32>>>(yin, t0b, f_gn1_g, f_gn1_b, 1);
        ode_conv_mma<<<BATCH, 256, MM_SMEM_BYTES>>>(t0b, t1b, w1hi, w1lo, f_conv1_b, S1, t);
        gn225_kernel<<<BATCH * 32, 32>>>(t1b, t1b, f_gn2_g, f_gn2_b, 1);
        ode_conv_mma<<<BATCH, 256, MM_SMEM_BYTES>>>(t1b, t2b, w2hi, w2lo, f_conv2_b, S2, t);
        gn225_kernel<<<BATCH * 32, 32>>>(t2b, kout, f_gn3_g, f_gn3_b, 0);
    };
    auto comb = [&](float* dst, const float* yin,
                    const float* p0, const float* p1, const float* p2,
                    const float* p3, const float* p4,
                    double c0, double c1, double c2, double c3, double c4, int n) {
        combine_kernel<<<3600, 256>>>((const float4*)yin, (float4*)dst,
            (const float4*)p0,
            (const float4*)(p1 ? p1 : p0), (const float4*)(p2 ? p2 : p0),
            (const float4*)(p3 ? p3 : p0), (const float4*)(p4 ? p4 : p0),
            (float)c0, (float)c1, (float)c2, (float)c3, (float)c4, n);
    };

    const double hs = 1.0 / 8.0;
    for (int st = 0; st < 8; st++) {
        double T0 = st * hs;
        feval((float)T0, y, kk[0]);
        comb(ytmp, y, kk[0], 0, 0, 0, 0, hs * (1.0 / 5.0), 0, 0, 0, 0, 1);
        feval((float)(T0 + hs / 5.0), ytmp, kk[1]);
        comb(ytmp, y, kk[0], kk[1], 0, 0, 0, hs * (3.0 / 40.0), hs * (9.0 / 40.0), 0, 0, 0, 2);
        feval((float)(T0 + 0.3 * hs), ytmp, kk[2]);
        comb(ytmp, y, kk[0], kk[1], kk[2], 0, 0,
             hs * (44.0 / 45.0), hs * (-56.0 / 15.0), hs * (32.0 / 9.0), 0, 0, 3);
        feval((float)(T0 + 0.8 * hs), ytmp, kk[3]);
        comb(ytmp, y, kk[0], kk[1], kk[2], kk[3], 0,
             hs * (19372.0 / 6561.0), hs * (-25360.0 / 2187.0),
             hs * (64448.0 / 6561.0), hs * (-212.0 / 729.0), 0, 4);
        feval((float)(T0 + (8.0 / 9.0) * hs), ytmp, kk[4]);
        comb(ytmp, y, kk[0], kk[1], kk[2], kk[3], kk[4],
             hs * (9017.0 / 3168.0), hs * (-355.0 / 33.0), hs * (46732.0 / 5247.0),
             hs * (49.0 / 176.0), hs * (-5103.0 / 18656.0), 5);
        feval((float)(T0 + hs), ytmp, kk[5]);
        comb(y, y, kk[0], kk[2], kk[3], kk[4], kk[5],
             hs * (35.0 / 384.0), hs * (500.0 / 1113.0), hs * (125.0 / 192.0),
             hs * (-2187.0 / 6784.0), hs * (11.0 / 84.0), 5);
    }

    // ---- head ----
    gn225_kernel<<<BATCH * 32, 32>>>(y, t0b, out_gn_g, out_gn_b, 1);
    pool_kernel<<<2048, 256>>>(t0b, pool);
    fc_kernel<<<BATCH, 64>>>(pool, fc_w, fc_b, out);
}